// round 15
// baseline (speedup 1.0000x reference)
#include <cuda_runtime.h>
#include <cuda_fp16.h>
#include <mma.h>
#include <cstdint>

using namespace nvcuda;

#define NN 4096
#define IN_DIM 128
#define HD 128          // HEADS*OUT_DIM
#define HEADS 4
#define PREP_ROWS 8
#define BN 160          // table width: 128 V + 4 w + 28 zero pad
#define BM 64           // i-tile rows per block
#define KB 64           // K per chunk
#define KSPLIT 4
#define KRANGE (NN / KSPLIT)     // 1024
#define CHUNKS (KRANGE / KB)     // 16
#define GT 256          // gemm threads (8 warps)

// smem strides (halfs), padded against bank conflicts
#define SA_LD 72
#define SB_LD 168
#define SA_BYTES (2 * BM * SA_LD * 2)        // 18432
#define SB_BYTES (2 * KB * SB_LD * 2)        // 43008
#define SMEM_TOTAL (SA_BYTES + SB_BYTES)     // 61440

// ---- scratch (__device__ globals, zero-initialized at module load) ----
__device__ __half g_Bt[NN * BN];             // [k][n]; cols 132.. never written -> 0
__device__ float  g_part[KSPLIT][NN][BN];    // K-split partials (fully overwritten)

// ---------------------------------------------------------------------------
// Kernel 1: prep. xp = x@W ; w = exp(scale*<xp,a_j>) ;
// g_Bt[k][n] = half(w[k,h(n)]*xp[k,n]) for n<128, g_Bt[k][128+h] = half(w[k,h]).
// ---------------------------------------------------------------------------
__global__ void __launch_bounds__(128) prep_kernel(const float* __restrict__ x,
                                                   const float* __restrict__ W,
                                                   const float* __restrict__ a) {
    int d    = threadIdx.x;
    int lane = d & 31;
    int h    = d >> 5;
    int row0 = blockIdx.x * PREP_ROWS;

    __shared__ float xs[PREP_ROWS][IN_DIM];
    {
        const float4* xg  = (const float4*)(x + (size_t)row0 * IN_DIM);
        float4*       xs4 = (float4*)xs;
        #pragma unroll
        for (int i = 0; i < PREP_ROWS * IN_DIM / 4 / 128; ++i)
            xs4[d + i * 128] = xg[d + i * 128];
    }
    float aj = a[lane];
    __syncthreads();

    float acc[PREP_ROWS];
    #pragma unroll
    for (int r = 0; r < PREP_ROWS; ++r) acc[r] = 0.f;

    const float* wcol = W + d;
    #pragma unroll
    for (int kc = 0; kc < IN_DIM; kc += 8) {
        float wv[8];
        #pragma unroll
        for (int u = 0; u < 8; ++u) wv[u] = wcol[(kc + u) * HD];
        #pragma unroll
        for (int u = 0; u < 8; ++u) {
            #pragma unroll
            for (int r = 0; r < PREP_ROWS; ++r)
                acc[r] = fmaf(xs[r][kc + u], wv[u], acc[r]);
        }
    }

    #pragma unroll
    for (int r = 0; r < PREP_ROWS; ++r) {
        float sv = acc[r] * aj;
        #pragma unroll
        for (int off = 16; off; off >>= 1)
            sv += __shfl_xor_sync(0xffffffffu, sv, off);
        float w = expf(sv * 0.17677669529663687f);   // 1/sqrt(32)
        int k = row0 + r;
        g_Bt[(size_t)k * BN + d] = __float2half(acc[r] * w);
        if (lane == 0) g_Bt[(size_t)k * BN + 128 + h] = __float2half(w);
    }
}

// ---------------------------------------------------------------------------
// Kernel 2: wmma GEMM. part[i, n] = sum_k adj[i, k] * Bt[k, n].
// Grid = 64 i-tiles x 4 K-splits. Block 256 thr (8 warps): warp (mt, nhalf)
// owns a 16-row m-tile x five 16-col n-tiles; accumulators live in registers
// across all 16 K-chunks. Double-buffered smem; adj fp32->fp16 in regs (exact).
// ---------------------------------------------------------------------------
__global__ void __launch_bounds__(GT) gemm_kernel(const float* __restrict__ adj) {
    extern __shared__ __align__(128) char smem[];
    __half* sA = (__half*)smem;                      // [2][BM][SA_LD]
    __half* sB = (__half*)(smem + SA_BYTES);         // [2][KB][SB_LD]

    int tid  = threadIdx.x;
    int wid  = tid >> 5;
    int s    = blockIdx.x >> 6;          // K-split 0..3
    int it   = blockIdx.x & 63;          // i-tile 0..63
    int i0   = it * BM;
    int k0b  = s * KRANGE;

    int mt = wid & 3;                    // m-tile (16 rows)
    int n0 = (wid >> 2) * 5;             // first of five n-tiles

    // adj load map: 16 threads cover one row's 64 floats (16 float4)
    int arow = tid >> 4;                 // 0..15 (+16u)
    int acol = tid & 15;

    wmma::fragment<wmma::accumulator, 16, 16, 16, float> facc[5];
    #pragma unroll
    for (int j = 0; j < 5; ++j) wmma::fill_fragment(facc[j], 0.f);

    float4 bv[4];                        // adj regs: 4 rows x 1 f4
    uint4  av[5];                        // table regs: 5 x 8 halfs

    auto load_regs = [&](int c) {
        int k0 = k0b + c * KB;
        const float4* asrc = (const float4*)(adj + (size_t)i0 * NN + k0);
        #pragma unroll
        for (int u = 0; u < 4; ++u)
            bv[u] = __ldcs(&asrc[(size_t)(arow + 16 * u) * (NN / 4) + acol]);
        #pragma unroll
        for (int p = 0; p < 5; ++p) {
            int id = tid + p * GT;       // 0..1279
            int kr = id / 20, nc = id % 20;
            av[p] = *(const uint4*)(g_Bt + (size_t)(k0 + kr) * BN + nc * 8);
        }
    };

    auto store_smem = [&](int b) {
        __half* pa = sA + b * BM * SA_LD;
        #pragma unroll
        for (int u = 0; u < 4; ++u) {
            __half2 h01 = __floats2half2_rn(bv[u].x, bv[u].y);
            __half2 h23 = __floats2half2_rn(bv[u].z, bv[u].w);
            __half2* dst = (__half2*)(pa + (arow + 16 * u) * SA_LD + acol * 4);
            dst[0] = h01; dst[1] = h23;
        }
        __half* pb = sB + b * KB * SB_LD;
        #pragma unroll
        for (int p = 0; p < 5; ++p) {
            int id = tid + p * GT;
            int kr = id / 20, nc = id % 20;
            *(uint4*)(pb + kr * SB_LD + nc * 8) = av[p];
        }
    };

    load_regs(0);
    store_smem(0);
    __syncthreads();

    for (int c = 0; c < CHUNKS; ++c) {
        int b = c & 1;
        if (c + 1 < CHUNKS) load_regs(c + 1);

        const __half* pa = sA + b * BM * SA_LD + mt * 16 * SA_LD;
        const __half* pb = sB + b * KB * SB_LD;
        #pragma unroll
        for (int ks = 0; ks < KB / 16; ++ks) {
            wmma::fragment<wmma::matrix_a, 16, 16, 16, __half, wmma::row_major> fa;
            wmma::load_matrix_sync(fa, pa + ks * 16, SA_LD);
            #pragma unroll
            for (int j = 0; j < 5; ++j) {
                wmma::fragment<wmma::matrix_b, 16, 16, 16, __half, wmma::row_major> fb;
                wmma::load_matrix_sync(fb, pb + ks * 16 * SB_LD + (n0 + j) * 16, SB_LD);
                wmma::mma_sync(facc[j], fa, fb, facc[j]);
            }
        }
        __syncthreads();
        if (c + 1 < CHUNKS) {
            store_smem((c + 1) & 1);
            __syncthreads();
        }
    }

    // epilogue: store partials directly to global
    float* base = &g_part[s][0][0];
    #pragma unroll
    for (int j = 0; j < 5; ++j) {
        float* dst = base + (size_t)(i0 + mt * 16) * BN + (n0 + j) * 16;
        wmma::store_matrix_sync(dst, facc[j], BN, wmma::mem_row_major);
    }
}

// ---------------------------------------------------------------------------
// Kernel 3: reduce. out[i][n] = sum_s p[s][i][n] / sum_s p[s][i][128+(n>>5)]
// Fixed split order -> deterministic.
// ---------------------------------------------------------------------------
__global__ void __launch_bounds__(256) reduce_kernel(float* __restrict__ out) {
    int idx = blockIdx.x * 256 + threadIdx.x;   // 4096*128 threads
    int i = idx >> 7, n = idx & 127;
    int dn = 128 + (n >> 5);
    float num = ((g_part[0][i][n]  + g_part[1][i][n]) +
                 (g_part[2][i][n]  + g_part[3][i][n]));
    float den = ((g_part[0][i][dn] + g_part[1][i][dn]) +
                 (g_part[2][i][dn] + g_part[3][i][dn]));
    out[idx] = num / den;
}

extern "C" void kernel_launch(void* const* d_in, const int* in_sizes, int n_in,
                              void* d_out, int out_size) {
    const float* x   = (const float*)d_in[0];   // [4096, 128]
    const float* adj = (const float*)d_in[1];   // [4096, 4096]
    const float* W   = (const float*)d_in[2];   // [128, 128]
    const float* a   = (const float*)d_in[3];   // [64]
    float* out = (float*)d_out;                 // [4096, 128]

    static int configured = 0;
    cudaFuncSetAttribute(gemm_kernel, cudaFuncAttributeMaxDynamicSharedMemorySize,
                         SMEM_TOTAL);
    (void)configured;

    prep_kernel<<<NN / PREP_ROWS, 128>>>(x, W, a);
    gemm_kernel<<<64 * KSPLIT, GT, SMEM_TOTAL>>>(adj);
    reduce_kernel<<<NN * HD / 256, 256>>>(out);
}